// round 11
// baseline (speedup 1.0000x reference)
#include <cuda_runtime.h>
#include <cuda_bf16.h>
#include <mma.h>
#include <math.h>
#include <cstdint>

using namespace nvcuda;

#define BATCH   1024
#define EMBD    512
#define RNND    512
#define GATES   2048
#define VOCABO  11998
#define VPAD    12032      // 188 * 64 (padded vocab, W pad rows zeroed)
#define FEATSD  4096
#define TSTEPS  15

typedef unsigned long long u64;

// ---------------- scratch (__device__ globals; no runtime allocation) ----------
__device__ float g_x[BATCH * EMBD];
__device__ float g_h[BATCH * RNND];
__device__ float g_c[BATCH * RNND];
__device__ float g_gates[BATCH * GATES];
__device__ float g_logits[BATCH * VPAD];
__device__ int   g_words[BATCH];
// bf16 exact-split operands for the WMMA logits GEMM
__device__ __nv_bfloat16 g_Whi[VPAD * RNND];
__device__ __nv_bfloat16 g_Wlo[VPAD * RNND];
__device__ __nv_bfloat16 g_hhi[BATCH * RNND];
__device__ __nv_bfloat16 g_hlo[BATCH * RNND];

// ---------------- packed f32x2 helpers (gates GEMM) -----------------------------
__device__ __forceinline__ u64 pack2(float lo, float hi) {
    u64 r; asm("mov.b64 %0, {%1, %2};" : "=l"(r) : "f"(lo), "f"(hi)); return r;
}
__device__ __forceinline__ void unpack2(u64 v, float& lo, float& hi) {
    asm("mov.b64 {%0, %1}, %2;" : "=f"(lo), "=f"(hi) : "l"(v));
}
__device__ __forceinline__ void ffma2(u64& d, u64 a, u64 b) {
    asm("fma.rn.f32x2 %0, %1, %2, %0;" : "+l"(d) : "l"(a), "l"(b));
}

// ---------------- activations ---------------------------------------------------
__device__ __forceinline__ float sigm_f(float x) { return 1.0f / (1.0f + expf(-x)); }
__device__ __forceinline__ float tanh_f(float x) {
    float e = expf(-2.0f * fabsf(x));
    float t = (1.0f - e) / (1.0f + e);
    return copysignf(t, x);
}

// ================================================================================
// Kernel 0: split W_out into bf16 hi/lo, zero-padded to VPAD rows.
// ================================================================================
__global__ void k_splitW(const float* __restrict__ Wout) {
    int idx = blockIdx.x * blockDim.x + threadIdx.x;   // VPAD*512 threads
    int row = idx >> 9, col = idx & 511;
    float w = (row < VOCABO) ? Wout[(size_t)row * RNND + col] : 0.0f;
    __nv_bfloat16 hi = __float2bfloat16(w);
    __nv_bfloat16 lo = __float2bfloat16(w - __bfloat162float(hi));
    g_Whi[idx] = hi;
    g_Wlo[idx] = lo;
}

// ================================================================================
// Kernel 1: g_x = relu(img @ W_feats^T + b); zero h, c.  (proven)
// ================================================================================
__global__ __launch_bounds__(256) void k_prime(const float* __restrict__ A,
                                               const float* __restrict__ Bw,
                                               const float* __restrict__ bias) {
    __shared__ float As[32][68];
    __shared__ float Bs[32][68];
    const int tid = threadIdx.x;
    const int bm = blockIdx.y * 64, bn = blockIdx.x * 64;
    const int lr = tid >> 3, lk = (tid & 7) << 2;
    const int m0 = (tid >> 4) << 2, n0 = (tid & 15) << 2;
    float acc[4][4] = {};

    for (int s = 0; s < FEATSD / 32; s++) {
        const int ka = s * 32 + lk;
        float4 a0 = *(const float4*)&A [(size_t)(bm + lr)      * FEATSD + ka];
        float4 a1 = *(const float4*)&A [(size_t)(bm + lr + 32) * FEATSD + ka];
        float4 b0 = *(const float4*)&Bw[(size_t)(bn + lr)      * FEATSD + ka];
        float4 b1 = *(const float4*)&Bw[(size_t)(bn + lr + 32) * FEATSD + ka];
        __syncthreads();
        As[lk+0][lr] = a0.x; As[lk+1][lr] = a0.y; As[lk+2][lr] = a0.z; As[lk+3][lr] = a0.w;
        As[lk+0][lr+32] = a1.x; As[lk+1][lr+32] = a1.y; As[lk+2][lr+32] = a1.z; As[lk+3][lr+32] = a1.w;
        Bs[lk+0][lr] = b0.x; Bs[lk+1][lr] = b0.y; Bs[lk+2][lr] = b0.z; Bs[lk+3][lr] = b0.w;
        Bs[lk+0][lr+32] = b1.x; Bs[lk+1][lr+32] = b1.y; Bs[lk+2][lr+32] = b1.z; Bs[lk+3][lr+32] = b1.w;
        __syncthreads();
        #pragma unroll
        for (int kk = 0; kk < 32; kk++) {
            float4 a = *(const float4*)&As[kk][m0];
            float4 b = *(const float4*)&Bs[kk][n0];
            acc[0][0] += a.x*b.x; acc[0][1] += a.x*b.y; acc[0][2] += a.x*b.z; acc[0][3] += a.x*b.w;
            acc[1][0] += a.y*b.x; acc[1][1] += a.y*b.y; acc[1][2] += a.y*b.z; acc[1][3] += a.y*b.w;
            acc[2][0] += a.z*b.x; acc[2][1] += a.z*b.y; acc[2][2] += a.z*b.z; acc[2][3] += a.z*b.w;
            acc[3][0] += a.w*b.x; acc[3][1] += a.w*b.y; acc[3][2] += a.w*b.z; acc[3][3] += a.w*b.w;
        }
    }

    #pragma unroll
    for (int i = 0; i < 4; i++) {
        int m = bm + m0 + i;
        #pragma unroll
        for (int j = 0; j < 4; j++) {
            int n = bn + n0 + j;
            float v = fmaxf(acc[i][j] + bias[n], 0.0f);
            int idx = m * EMBD + n;
            g_x[idx] = v;
            g_h[idx] = 0.0f;
            g_c[idx] = 0.0f;
        }
    }
}

// ================================================================================
// Kernel 2: LSTM gates GEMM (f32x2 packed, proven R9). grid(16,8), 256 thr.
// ================================================================================
__global__ __launch_bounds__(256) void k_gates(const float* __restrict__ Wih,
                                               const float* __restrict__ Whh,
                                               const float* __restrict__ bih,
                                               const float* __restrict__ bhh) {
    __shared__ __align__(16) float As[32][132];
    __shared__ __align__(16) float Bs[32][132];
    const int tid = threadIdx.x;
    const int bm = blockIdx.y * 128, bn = blockIdx.x * 128;
    const int lr = tid >> 3;
    const int lk = (tid & 7) << 2;
    const int m0 = (tid >> 4) << 2;
    const int n0 = (tid & 15) << 2;
    u64 acc2[8][4] = {};

    for (int s = 0; s < 32; s++) {
        const int sk = s * 32;
        const float* Ap = (sk < 512) ? g_x : g_h;
        const float* Bp = (sk < 512) ? Wih : Whh;
        const int ka = (sk & 511) + lk;
        float4 ga[4], gb[4];
        #pragma unroll
        for (int u = 0; u < 4; u++) {
            ga[u] = *(const float4*)&Ap[(size_t)(bm + lr + 32*u) * 512 + ka];
            gb[u] = *(const float4*)&Bp[(size_t)(bn + lr + 32*u) * 512 + ka];
        }
        __syncthreads();
        #pragma unroll
        for (int u = 0; u < 4; u++) {
            int rr = lr + 32*u;
            As[lk+0][rr] = ga[u].x; As[lk+1][rr] = ga[u].y;
            As[lk+2][rr] = ga[u].z; As[lk+3][rr] = ga[u].w;
            Bs[lk+0][rr] = gb[u].x; Bs[lk+1][rr] = gb[u].y;
            Bs[lk+2][rr] = gb[u].z; Bs[lk+3][rr] = gb[u].w;
        }
        __syncthreads();
        #pragma unroll
        for (int kk = 0; kk < 32; kk++) {
            float4 a0 = *(const float4*)&As[kk][m0];
            float4 a1 = *(const float4*)&As[kk][m0 + 64];
            ulonglong2 b0 = *(const ulonglong2*)&Bs[kk][n0];
            ulonglong2 b1 = *(const ulonglong2*)&Bs[kk][n0 + 64];
            u64 av[8];
            av[0] = pack2(a0.x, a0.x); av[1] = pack2(a0.y, a0.y);
            av[2] = pack2(a0.z, a0.z); av[3] = pack2(a0.w, a0.w);
            av[4] = pack2(a1.x, a1.x); av[5] = pack2(a1.y, a1.y);
            av[6] = pack2(a1.z, a1.z); av[7] = pack2(a1.w, a1.w);
            u64 bv[4] = { b0.x, b0.y, b1.x, b1.y };
            #pragma unroll
            for (int i = 0; i < 8; i++)
                #pragma unroll
                for (int j = 0; j < 4; j++)
                    ffma2(acc2[i][j], av[i], bv[j]);
        }
    }

    #pragma unroll
    for (int i = 0; i < 8; i++) {
        int m = bm + m0 + ((i < 4) ? i : 60 + i);
        #pragma unroll
        for (int j = 0; j < 4; j++) {
            int n = bn + n0 + ((j < 2) ? 2*j : 60 + 2*j);
            float lo, hi; unpack2(acc2[i][j], lo, hi);
            g_gates[m * GATES + n]     = lo + bih[n]     + bhh[n];
            g_gates[m * GATES + n + 1] = hi + bih[n + 1] + bhh[n + 1];
        }
    }
}

// ================================================================================
// Kernel 3: logits GEMM on WMMA bf16 (HMMA), 3-product exact split.
// Block: 128 (batch) x 64 (vocab), 8 warps, each warp 32x32 (2x2 m16n16k16).
// BK = 32, K = 512. grid(188, 8). Bias is added later in k_argmax.
// ================================================================================
#define LDT 40   // smem row stride in bf16 elems (80 B, 16B-aligned)

__global__ __launch_bounds__(256) void k_logits_wmma() {
    __shared__ __align__(16) __nv_bfloat16 sAhi[128][LDT];
    __shared__ __align__(16) __nv_bfloat16 sAlo[128][LDT];
    __shared__ __align__(16) __nv_bfloat16 sBhi[64][LDT];
    __shared__ __align__(16) __nv_bfloat16 sBlo[64][LDT];

    const int tid = threadIdx.x;
    const int bm = blockIdx.y * 128;     // batch rows
    const int bn = blockIdx.x * 64;      // vocab rows (padded; W pad zeroed)
    const int w  = tid >> 5;
    const int wm = (w >> 1) * 32;        // warp row offset in tile (0..96)
    const int wn = (w & 1) * 32;         // warp col offset in tile (0 or 32)

    wmma::fragment<wmma::accumulator, 16, 16, 16, float> acc[2][2];
    #pragma unroll
    for (int i = 0; i < 2; i++)
        #pragma unroll
        for (int j = 0; j < 2; j++)
            wmma::fill_fragment(acc[i][j], 0.0f);

    for (int c = 0; c < 16; c++) {
        const int kc = c * 32;
        __syncthreads();   // protect previous iteration's fragment reads
        // A tiles: 128x32 hi & lo. 512 16B-chunks each; 256 thr x 2.
        #pragma unroll
        for (int it = 0; it < 2; it++) {
            int chunk = tid + it * 256;          // 0..511
            int row = chunk >> 2, col8 = (chunk & 3) * 8;
            *(uint4*)&sAhi[row][col8] =
                *(const uint4*)&g_hhi[(size_t)(bm + row) * RNND + kc + col8];
            *(uint4*)&sAlo[row][col8] =
                *(const uint4*)&g_hlo[(size_t)(bm + row) * RNND + kc + col8];
        }
        // B tiles: 64x32 hi & lo. 256 chunks each; 1 per thread.
        {
            int row = tid >> 2, col8 = (tid & 3) * 8;
            *(uint4*)&sBhi[row][col8] =
                *(const uint4*)&g_Whi[(size_t)(bn + row) * RNND + kc + col8];
            *(uint4*)&sBlo[row][col8] =
                *(const uint4*)&g_Wlo[(size_t)(bn + row) * RNND + kc + col8];
        }
        __syncthreads();

        #pragma unroll
        for (int ks = 0; ks < 2; ks++) {
            wmma::fragment<wmma::matrix_a, 16, 16, 16, __nv_bfloat16, wmma::row_major> ahi[2], alo[2];
            wmma::fragment<wmma::matrix_b, 16, 16, 16, __nv_bfloat16, wmma::col_major> bhi[2], blo[2];
            #pragma unroll
            for (int i = 0; i < 2; i++) {
                wmma::load_matrix_sync(ahi[i], &sAhi[wm + 16*i][ks*16], LDT);
                wmma::load_matrix_sync(alo[i], &sAlo[wm + 16*i][ks*16], LDT);
            }
            #pragma unroll
            for (int j = 0; j < 2; j++) {
                wmma::load_matrix_sync(bhi[j], &sBhi[wn + 16*j][ks*16], LDT);
                wmma::load_matrix_sync(blo[j], &sBlo[wn + 16*j][ks*16], LDT);
            }
            #pragma unroll
            for (int i = 0; i < 2; i++)
                #pragma unroll
                for (int j = 0; j < 2; j++) {
                    wmma::mma_sync(acc[i][j], ahi[i], bhi[j], acc[i][j]);
                    wmma::mma_sync(acc[i][j], ahi[i], blo[j], acc[i][j]);
                    wmma::mma_sync(acc[i][j], alo[i], bhi[j], acc[i][j]);
                }
        }
    }

    #pragma unroll
    for (int i = 0; i < 2; i++)
        #pragma unroll
        for (int j = 0; j < 2; j++) {
            float* dst = &g_logits[(size_t)(bm + wm + 16*i) * VPAD + bn + wn + 16*j];
            wmma::store_matrix_sync(dst, acc[i][j], VPAD, wmma::mem_row_major);
        }
}

// -------- Kernel 4: LSTM pointwise + bf16 split of h ----------------------------
__global__ void k_point() {
    int idx = blockIdx.x * blockDim.x + threadIdx.x;
    int b = idx >> 9, n = idx & 511;
    const float* g = g_gates + b * GATES;
    float ig = sigm_f(g[n]);
    float fg = sigm_f(g[512 + n]);
    float gg = tanh_f(g[1024 + n]);
    float og = sigm_f(g[1536 + n]);
    float c = fg * g_c[idx] + ig * gg;
    g_c[idx] = c;
    float h = og * tanh_f(c);
    g_h[idx] = h;
    __nv_bfloat16 hi = __float2bfloat16(h);
    g_hhi[idx] = hi;
    g_hlo[idx] = __float2bfloat16(h - __bfloat162float(hi));
}

// -------- Kernel 5: embedding gather -------------------------------------------
__global__ void k_embed(const float* __restrict__ emb, int t) {
    int b = blockIdx.x;
    int w = (t == 0) ? 1 : g_words[b];
    const float4* src = (const float4*)(emb + (size_t)w * EMBD);
    float4* dst = (float4*)(g_x + (size_t)b * EMBD);
    dst[threadIdx.x] = src[threadIdx.x];
}

// -------- Kernel 6: per-row argmax (+ bias), float32 output ---------------------
__global__ __launch_bounds__(256) void k_argmax(const float* __restrict__ bout,
                                                float* __restrict__ out, int t) {
    __shared__ float sv[256];
    __shared__ int   si[256];
    const int b = blockIdx.x;
    const int tid = threadIdx.x;
    const float* row = g_logits + (size_t)b * VPAD;

    float bv = -1e30f;
    int bi = 0;
    for (int n = tid; n < VOCABO; n += 256) {
        float v = row[n] + bout[n];
        if (v > bv) { bv = v; bi = n; }
    }
    sv[tid] = bv; si[tid] = bi;
    __syncthreads();
    for (int s = 128; s > 0; s >>= 1) {
        if (tid < s) {
            float ov = sv[tid + s]; int oi = si[tid + s];
            if (ov > sv[tid] || (ov == sv[tid] && oi < si[tid])) {
                sv[tid] = ov; si[tid] = oi;
            }
        }
        __syncthreads();
    }
    if (tid == 0) {
        out[b * TSTEPS + t] = (float)si[0];
        g_words[b] = si[0] + 2;
    }
}

// ================================================================================
extern "C" void kernel_launch(void* const* d_in, const int* in_sizes, int n_in,
                              void* d_out, int out_size) {
    const float *img = 0, *W_feats = 0, *b_feats = 0, *W_ih = 0, *W_hh = 0,
                *b_ih = 0, *b_hh = 0, *emb = 0, *W_out = 0, *b_out = 0;
    for (int i = 0; i < n_in; i++) {
        const float* p = (const float*)d_in[i];
        switch (in_sizes[i]) {
            case 4194304: img = p; break;
            case 2097152: W_feats = p; break;
            case 512:     b_feats = p; break;
            case 1048576: if (!W_ih) W_ih = p; else W_hh = p; break;
            case 2048:    if (!b_ih) b_ih = p; else b_hh = p; break;
            case 6144000: emb = p; break;
            case 6142976: W_out = p; break;
            case 11998:   b_out = p; break;
            default: break;
        }
    }
    if (!img || !W_feats || !b_feats || !W_ih || !W_hh || !b_ih || !b_hh ||
        !emb || !W_out || !b_out) {
        img     = (const float*)d_in[0];
        W_feats = (const float*)d_in[1];
        b_feats = (const float*)d_in[2];
        W_ih    = (const float*)d_in[3];
        W_hh    = (const float*)d_in[4];
        b_ih    = (const float*)d_in[5];
        b_hh    = (const float*)d_in[6];
        emb     = (const float*)d_in[7];
        W_out   = (const float*)d_in[8];
        b_out   = (const float*)d_in[9];
    }
    float* out = (float*)d_out;

    k_splitW<<<(VPAD * RNND) / 256, 256>>>(W_out);
    k_prime <<<dim3(8, 16),  256>>>(img, W_feats, b_feats);
    k_gates <<<dim3(16, 8),  256>>>(W_ih, W_hh, b_ih, b_hh);
    k_point <<<2048, 256>>>();

    for (int t = 0; t < TSTEPS; t++) {
        k_embed       <<<1024, 128>>>(emb, t);
        k_gates       <<<dim3(16, 8), 256>>>(W_ih, W_hh, b_ih, b_hh);
        k_point       <<<2048, 256>>>();
        k_logits_wmma <<<dim3(188, 8), 256>>>();
        k_argmax      <<<1024, 256>>>(b_out, out, t);
    }
}

// round 12
// speedup vs baseline: 1.4061x; 1.4061x over previous
#include <cuda_runtime.h>
#include <math.h>
#include <cstdint>

#define BATCH   1024
#define EMBD    512
#define RNND    512
#define GATES   2048
#define VOCABO  11998
#define FEATSD  4096
#define TSTEPS  15

typedef unsigned long long u64;

// ---------------- scratch (__device__ globals; no runtime allocation) ----------
__device__ float g_x[BATCH * EMBD];
__device__ float g_h[BATCH * RNND];
__device__ float g_c[BATCH * RNND];
__device__ float g_gates[BATCH * GATES];
__device__ u64   g_amax[BATCH];
__device__ int   g_words[BATCH];

// ---------------- packed f32x2 helpers ------------------------------------------
__device__ __forceinline__ u64 pack2(float lo, float hi) {
    u64 r; asm("mov.b64 %0, {%1, %2};" : "=l"(r) : "f"(lo), "f"(hi)); return r;
}
__device__ __forceinline__ void unpack2(u64 v, float& lo, float& hi) {
    asm("mov.b64 {%0, %1}, %2;" : "=f"(lo), "=f"(hi) : "l"(v));
}
__device__ __forceinline__ void ffma2(u64& d, u64 a, u64 b) {
    asm("fma.rn.f32x2 %0, %1, %2, %0;" : "+l"(d) : "l"(a), "l"(b));
}

// ---------------- activations ---------------------------------------------------
__device__ __forceinline__ float sigm_f(float x) { return 1.0f / (1.0f + expf(-x)); }
__device__ __forceinline__ float tanh_f(float x) {
    float e = expf(-2.0f * fabsf(x));
    float t = (1.0f - e) / (1.0f + e);
    return copysignf(t, x);
}

// ================================================================================
// Kernel 1: g_x = relu(img[1024,4096] @ W_feats^T + b); zero h, c.
// 64x64 tile, BK=32, 256 thr, FFMA2 4x4/thread. grid(8,16).
// ================================================================================
__global__ __launch_bounds__(256) void k_prime(const float* __restrict__ A,
                                               const float* __restrict__ Bw,
                                               const float* __restrict__ bias) {
    __shared__ __align__(16) float As[32][68];
    __shared__ __align__(16) float Bs[32][68];
    const int tid = threadIdx.x;
    const int bm = blockIdx.y * 64, bn = blockIdx.x * 64;
    const int lr = tid >> 3, lk = (tid & 7) << 2;
    const int m0 = (tid >> 4) << 2, n0 = (tid & 15) << 2;
    u64 acc2[4][2] = {};

    for (int s = 0; s < FEATSD / 32; s++) {
        const int ka = s * 32 + lk;
        float4 a0 = *(const float4*)&A [(size_t)(bm + lr)      * FEATSD + ka];
        float4 a1 = *(const float4*)&A [(size_t)(bm + lr + 32) * FEATSD + ka];
        float4 b0 = *(const float4*)&Bw[(size_t)(bn + lr)      * FEATSD + ka];
        float4 b1 = *(const float4*)&Bw[(size_t)(bn + lr + 32) * FEATSD + ka];
        __syncthreads();
        As[lk+0][lr] = a0.x; As[lk+1][lr] = a0.y; As[lk+2][lr] = a0.z; As[lk+3][lr] = a0.w;
        As[lk+0][lr+32] = a1.x; As[lk+1][lr+32] = a1.y; As[lk+2][lr+32] = a1.z; As[lk+3][lr+32] = a1.w;
        Bs[lk+0][lr] = b0.x; Bs[lk+1][lr] = b0.y; Bs[lk+2][lr] = b0.z; Bs[lk+3][lr] = b0.w;
        Bs[lk+0][lr+32] = b1.x; Bs[lk+1][lr+32] = b1.y; Bs[lk+2][lr+32] = b1.z; Bs[lk+3][lr+32] = b1.w;
        __syncthreads();
        #pragma unroll
        for (int kk = 0; kk < 32; kk++) {
            float4 a = *(const float4*)&As[kk][m0];
            ulonglong2 b = *(const ulonglong2*)&Bs[kk][n0];
            u64 av[4] = { pack2(a.x, a.x), pack2(a.y, a.y),
                          pack2(a.z, a.z), pack2(a.w, a.w) };
            #pragma unroll
            for (int i = 0; i < 4; i++) {
                ffma2(acc2[i][0], av[i], b.x);
                ffma2(acc2[i][1], av[i], b.y);
            }
        }
    }

    #pragma unroll
    for (int i = 0; i < 4; i++) {
        int m = bm + m0 + i;
        #pragma unroll
        for (int j = 0; j < 2; j++) {
            int n = bn + n0 + 2 * j;
            float lo, hi; unpack2(acc2[i][j], lo, hi);
            int idx = m * EMBD + n;
            g_x[idx]     = fmaxf(lo + bias[n],     0.0f);
            g_x[idx + 1] = fmaxf(hi + bias[n + 1], 0.0f);
            g_h[idx] = 0.0f; g_h[idx + 1] = 0.0f;
            g_c[idx] = 0.0f; g_c[idx + 1] = 0.0f;
        }
    }
}

// ================================================================================
// Kernel 2: LSTM gates GEMM, FFMA2, double-buffered BK=16.
// g_gates = [g_x | g_h] @ [W_ih | W_hh]^T + b_ih + b_hh. 128x128 tile. grid(16,8).
// Load map: lr = tid>>2 (0..63) rows lr, lr+64; lk = (tid&3)<<2.
// ================================================================================
__global__ __launch_bounds__(256) void k_gates(const float* __restrict__ Wih,
                                               const float* __restrict__ Whh,
                                               const float* __restrict__ bih,
                                               const float* __restrict__ bhh) {
    __shared__ __align__(16) float As[2][16][132];
    __shared__ __align__(16) float Bs[2][16][132];
    const int tid = threadIdx.x;
    const int bm = blockIdx.y * 128, bn = blockIdx.x * 128;
    const int lr = tid >> 2;              // 0..63
    const int lk = (tid & 3) << 2;        // 0,4,8,12
    const int m0 = (tid >> 4) << 2;
    const int n0 = (tid & 15) << 2;
    u64 acc2[8][4] = {};
    float4 ra0, ra1, rb0, rb1;

    // preload slab 0 (from g_x / Wih)
    ra0 = *(const float4*)&g_x[(size_t)(bm + lr)      * 512 + lk];
    ra1 = *(const float4*)&g_x[(size_t)(bm + lr + 64) * 512 + lk];
    rb0 = *(const float4*)&Wih[(size_t)(bn + lr)      * 512 + lk];
    rb1 = *(const float4*)&Wih[(size_t)(bn + lr + 64) * 512 + lk];
    int buf = 0;
    As[0][lk+0][lr] = ra0.x; As[0][lk+1][lr] = ra0.y; As[0][lk+2][lr] = ra0.z; As[0][lk+3][lr] = ra0.w;
    As[0][lk+0][lr+64] = ra1.x; As[0][lk+1][lr+64] = ra1.y; As[0][lk+2][lr+64] = ra1.z; As[0][lk+3][lr+64] = ra1.w;
    Bs[0][lk+0][lr] = rb0.x; Bs[0][lk+1][lr] = rb0.y; Bs[0][lk+2][lr] = rb0.z; Bs[0][lk+3][lr] = rb0.w;
    Bs[0][lk+0][lr+64] = rb1.x; Bs[0][lk+1][lr+64] = rb1.y; Bs[0][lk+2][lr+64] = rb1.z; Bs[0][lk+3][lr+64] = rb1.w;
    __syncthreads();

    const int S = 64;                     // virtual K = 1024, BK = 16
    for (int s = 1; s <= S; s++) {
        if (s < S) {
            const int sk = s * 16;
            const float* Ap = (sk < 512) ? g_x : g_h;
            const float* Bp = (sk < 512) ? Wih : Whh;
            const int ka = (sk & 511) + lk;
            ra0 = *(const float4*)&Ap[(size_t)(bm + lr)      * 512 + ka];
            ra1 = *(const float4*)&Ap[(size_t)(bm + lr + 64) * 512 + ka];
            rb0 = *(const float4*)&Bp[(size_t)(bn + lr)      * 512 + ka];
            rb1 = *(const float4*)&Bp[(size_t)(bn + lr + 64) * 512 + ka];
        }
        #pragma unroll
        for (int kk = 0; kk < 16; kk++) {
            float4 a0 = *(const float4*)&As[buf][kk][m0];
            float4 a1 = *(const float4*)&As[buf][kk][m0 + 64];
            ulonglong2 b0 = *(const ulonglong2*)&Bs[buf][kk][n0];
            ulonglong2 b1 = *(const ulonglong2*)&Bs[buf][kk][n0 + 64];
            u64 av[8] = { pack2(a0.x, a0.x), pack2(a0.y, a0.y),
                          pack2(a0.z, a0.z), pack2(a0.w, a0.w),
                          pack2(a1.x, a1.x), pack2(a1.y, a1.y),
                          pack2(a1.z, a1.z), pack2(a1.w, a1.w) };
            u64 bv[4] = { b0.x, b0.y, b1.x, b1.y };
            #pragma unroll
            for (int i = 0; i < 8; i++)
                #pragma unroll
                for (int j = 0; j < 4; j++)
                    ffma2(acc2[i][j], av[i], bv[j]);
        }
        if (s < S) {
            buf ^= 1;
            As[buf][lk+0][lr] = ra0.x; As[buf][lk+1][lr] = ra0.y; As[buf][lk+2][lr] = ra0.z; As[buf][lk+3][lr] = ra0.w;
            As[buf][lk+0][lr+64] = ra1.x; As[buf][lk+1][lr+64] = ra1.y; As[buf][lk+2][lr+64] = ra1.z; As[buf][lk+3][lr+64] = ra1.w;
            Bs[buf][lk+0][lr] = rb0.x; Bs[buf][lk+1][lr] = rb0.y; Bs[buf][lk+2][lr] = rb0.z; Bs[buf][lk+3][lr] = rb0.w;
            Bs[buf][lk+0][lr+64] = rb1.x; Bs[buf][lk+1][lr+64] = rb1.y; Bs[buf][lk+2][lr+64] = rb1.z; Bs[buf][lk+3][lr+64] = rb1.w;
            __syncthreads();
        }
    }

    #pragma unroll
    for (int i = 0; i < 8; i++) {
        int m = bm + m0 + ((i < 4) ? i : 60 + i);
        #pragma unroll
        for (int j = 0; j < 4; j++) {
            int n = bn + n0 + ((j < 2) ? 2*j : 60 + 2*j);
            float lo, hi; unpack2(acc2[i][j], lo, hi);
            g_gates[m * GATES + n]     = lo + bih[n]     + bhh[n];
            g_gates[m * GATES + n + 1] = hi + bih[n + 1] + bhh[n + 1];
        }
    }
}

// ================================================================================
// Kernel 3: logits GEMM + FUSED argmax. No logits materialization.
// D = g_h @ W_out^T + b_out ; per-row packed-key argmax -> g_amax.
// Key = (sortable_f32 << 32) | (0xFFFFFFFF - n): max key = max value, min index.
// 128x128 tile, double-buffered BK=16, FFMA2. grid(94,8).
// ================================================================================
__global__ __launch_bounds__(256) void k_logits_f(const float* __restrict__ Wout,
                                                  const float* __restrict__ bout) {
    __shared__ __align__(16) float As[2][16][132];
    __shared__ __align__(16) float Bs[2][16][132];
    __shared__ u64 sBest[128];
    const int tid = threadIdx.x;
    const int bm = blockIdx.y * 128, bn = blockIdx.x * 128;
    const int lr = tid >> 2;
    const int lk = (tid & 3) << 2;
    const int m0 = (tid >> 4) << 2;
    const int n0 = (tid & 15) << 2;
    u64 acc2[8][4] = {};
    float4 ra0, ra1, rb0, rb1;
    const float4 z4 = make_float4(0.f, 0.f, 0.f, 0.f);
    const int br0 = bn + lr, br1 = bn + lr + 64;
    const bool v0 = br0 < VOCABO, v1 = br1 < VOCABO;

    if (tid < 128) sBest[tid] = 0ULL;

    ra0 = *(const float4*)&g_h[(size_t)(bm + lr)      * 512 + lk];
    ra1 = *(const float4*)&g_h[(size_t)(bm + lr + 64) * 512 + lk];
    rb0 = v0 ? *(const float4*)&Wout[(size_t)br0 * 512 + lk] : z4;
    rb1 = v1 ? *(const float4*)&Wout[(size_t)br1 * 512 + lk] : z4;
    int buf = 0;
    As[0][lk+0][lr] = ra0.x; As[0][lk+1][lr] = ra0.y; As[0][lk+2][lr] = ra0.z; As[0][lk+3][lr] = ra0.w;
    As[0][lk+0][lr+64] = ra1.x; As[0][lk+1][lr+64] = ra1.y; As[0][lk+2][lr+64] = ra1.z; As[0][lk+3][lr+64] = ra1.w;
    Bs[0][lk+0][lr] = rb0.x; Bs[0][lk+1][lr] = rb0.y; Bs[0][lk+2][lr] = rb0.z; Bs[0][lk+3][lr] = rb0.w;
    Bs[0][lk+0][lr+64] = rb1.x; Bs[0][lk+1][lr+64] = rb1.y; Bs[0][lk+2][lr+64] = rb1.z; Bs[0][lk+3][lr+64] = rb1.w;
    __syncthreads();

    const int S = 32;                     // K = 512, BK = 16
    for (int s = 1; s <= S; s++) {
        if (s < S) {
            const int ka = s * 16 + lk;
            ra0 = *(const float4*)&g_h[(size_t)(bm + lr)      * 512 + ka];
            ra1 = *(const float4*)&g_h[(size_t)(bm + lr + 64) * 512 + ka];
            rb0 = v0 ? *(const float4*)&Wout[(size_t)br0 * 512 + ka] : z4;
            rb1 = v1 ? *(const float4*)&Wout[(size_t)br1 * 512 + ka] : z4;
        }
        #pragma unroll
        for (int kk = 0; kk < 16; kk++) {
            float4 a0 = *(const float4*)&As[buf][kk][m0];
            float4 a1 = *(const float4*)&As[buf][kk][m0 + 64];
            ulonglong2 b0 = *(const ulonglong2*)&Bs[buf][kk][n0];
            ulonglong2 b1 = *(const ulonglong2*)&Bs[buf][kk][n0 + 64];
            u64 av[8] = { pack2(a0.x, a0.x), pack2(a0.y, a0.y),
                          pack2(a0.z, a0.z), pack2(a0.w, a0.w),
                          pack2(a1.x, a1.x), pack2(a1.y, a1.y),
                          pack2(a1.z, a1.z), pack2(a1.w, a1.w) };
            u64 bv[4] = { b0.x, b0.y, b1.x, b1.y };
            #pragma unroll
            for (int i = 0; i < 8; i++)
                #pragma unroll
                for (int j = 0; j < 4; j++)
                    ffma2(acc2[i][j], av[i], bv[j]);
        }
        if (s < S) {
            buf ^= 1;
            As[buf][lk+0][lr] = ra0.x; As[buf][lk+1][lr] = ra0.y; As[buf][lk+2][lr] = ra0.z; As[buf][lk+3][lr] = ra0.w;
            As[buf][lk+0][lr+64] = ra1.x; As[buf][lk+1][lr+64] = ra1.y; As[buf][lk+2][lr+64] = ra1.z; As[buf][lk+3][lr+64] = ra1.w;
            Bs[buf][lk+0][lr] = rb0.x; Bs[buf][lk+1][lr] = rb0.y; Bs[buf][lk+2][lr] = rb0.z; Bs[buf][lk+3][lr] = rb0.w;
            Bs[buf][lk+0][lr+64] = rb1.x; Bs[buf][lk+1][lr+64] = rb1.y; Bs[buf][lk+2][lr+64] = rb1.z; Bs[buf][lk+3][lr+64] = rb1.w;
            __syncthreads();
        }
    }
    __syncthreads();   // sBest init + last compute complete

    // ---- fused argmax epilogue --------------------------------------------------
    #pragma unroll
    for (int i = 0; i < 8; i++) {
        const int mloc = m0 + ((i < 4) ? i : 60 + i);
        u64 best = 0ULL;
        #pragma unroll
        for (int j = 0; j < 4; j++) {
            int n = bn + n0 + ((j < 2) ? 2*j : 60 + 2*j);
            float lo, hi; unpack2(acc2[i][j], lo, hi);
            if (n < VOCABO) {
                float v = lo + bout[n];
                unsigned u = __float_as_uint(v);
                u = (u & 0x80000000u) ? ~u : (u | 0x80000000u);
                u64 key = ((u64)u << 32) | (u64)(0xFFFFFFFFu - (unsigned)n);
                if (key > best) best = key;
            }
            if (n + 1 < VOCABO) {
                float v = hi + bout[n + 1];
                unsigned u = __float_as_uint(v);
                u = (u & 0x80000000u) ? ~u : (u | 0x80000000u);
                u64 key = ((u64)u << 32) | (u64)(0xFFFFFFFFu - (unsigned)(n + 1));
                if (key > best) best = key;
            }
        }
        atomicMax(&sBest[mloc], best);
    }
    __syncthreads();
    if (tid < 128) atomicMax(&g_amax[bm + tid], sBest[tid]);
}

// -------- Kernel 4: LSTM pointwise + argmax accumulator reset -------------------
__global__ void k_point() {
    int idx = blockIdx.x * blockDim.x + threadIdx.x;
    int b = idx >> 9, n = idx & 511;
    const float* g = g_gates + b * GATES;
    float ig = sigm_f(g[n]);
    float fg = sigm_f(g[512 + n]);
    float gg = tanh_f(g[1024 + n]);
    float og = sigm_f(g[1536 + n]);
    float c = fg * g_c[idx] + ig * gg;
    g_c[idx] = c;
    g_h[idx] = og * tanh_f(c);
    if (idx < BATCH) g_amax[idx] = 0ULL;
}

// -------- Kernel 5: embedding gather -------------------------------------------
__global__ void k_embed(const float* __restrict__ emb, int t) {
    int b = blockIdx.x;
    int w = (t == 0) ? 1 : g_words[b];
    const float4* src = (const float4*)(emb + (size_t)w * EMBD);
    float4* dst = (float4*)(g_x + (size_t)b * EMBD);
    dst[threadIdx.x] = src[threadIdx.x];
}

// -------- Kernel 6: decode packed key -> output token + next word ---------------
__global__ void k_finish(float* __restrict__ out, int t) {
    int b = blockIdx.x * blockDim.x + threadIdx.x;
    if (b < BATCH) {
        u64 key = g_amax[b];
        int idx = (int)(0xFFFFFFFFu - (unsigned)(key & 0xFFFFFFFFull));
        out[b * TSTEPS + t] = (float)idx;
        g_words[b] = idx + 2;
    }
}

// ================================================================================
extern "C" void kernel_launch(void* const* d_in, const int* in_sizes, int n_in,
                              void* d_out, int out_size) {
    const float *img = 0, *W_feats = 0, *b_feats = 0, *W_ih = 0, *W_hh = 0,
                *b_ih = 0, *b_hh = 0, *emb = 0, *W_out = 0, *b_out = 0;
    for (int i = 0; i < n_in; i++) {
        const float* p = (const float*)d_in[i];
        switch (in_sizes[i]) {
            case 4194304: img = p; break;
            case 2097152: W_feats = p; break;
            case 512:     b_feats = p; break;
            case 1048576: if (!W_ih) W_ih = p; else W_hh = p; break;
            case 2048:    if (!b_ih) b_ih = p; else b_hh = p; break;
            case 6144000: emb = p; break;
            case 6142976: W_out = p; break;
            case 11998:   b_out = p; break;
            default: break;
        }
    }
    if (!img || !W_feats || !b_feats || !W_ih || !W_hh || !b_ih || !b_hh ||
        !emb || !W_out || !b_out) {
        img     = (const float*)d_in[0];
        W_feats = (const float*)d_in[1];
        b_feats = (const float*)d_in[2];
        W_ih    = (const float*)d_in[3];
        W_hh    = (const float*)d_in[4];
        b_ih    = (const float*)d_in[5];
        b_hh    = (const float*)d_in[6];
        emb     = (const float*)d_in[7];
        W_out   = (const float*)d_in[8];
        b_out   = (const float*)d_in[9];
    }
    float* out = (float*)d_out;

    k_prime <<<dim3(8, 16), 256>>>(img, W_feats, b_feats);
    k_gates <<<dim3(16, 8), 256>>>(W_ih, W_hh, b_ih, b_hh);
    k_point <<<2048, 256>>>();

    for (int t = 0; t < TSTEPS; t++) {
        k_embed    <<<1024, 128>>>(emb, t);
        k_gates    <<<dim3(16, 8), 256>>>(W_ih, W_hh, b_ih, b_hh);
        k_point    <<<2048, 256>>>();
        k_logits_f <<<dim3(94, 8), 256>>>(W_out, b_out);
        k_finish   <<<4, 256>>>(out, t);
    }
}